// round 1
// baseline (speedup 1.0000x reference)
#include <cuda_runtime.h>
#include <cuda_bf16.h>

#define Bn 32
#define Nn 8192
#define Gn 256
#define Kn 32
#define FULLMASK 0xFFFFFFFFu

// ---------------------------------------------------------------------------
// Kernel 1: farthest point sampling. One block per batch, 1024 threads.
// Points and running min-dist live in registers (8 points / thread).
// Argmax with first-index tie-break via packed (dist_bits<<32)|(N-1-idx) max.
// ---------------------------------------------------------------------------
__global__ __launch_bounds__(1024, 1) void fps_kernel(const float* __restrict__ xyz,
                                                      float* __restrict__ centers)
{
    __shared__ unsigned long long warpbest[32];
    __shared__ unsigned long long finalbest;

    const int b    = blockIdx.x;
    const int tid  = threadIdx.x;
    const int lane = tid & 31;
    const int wid  = tid >> 5;
    const float* xb = xyz + (long)b * Nn * 3;

    float px[8], py[8], pz[8], mind[8];
#pragma unroll
    for (int i = 0; i < 8; i++) {
        int p = tid * 8 + i;
        px[i] = xb[3 * p + 0];
        py[i] = xb[3 * p + 1];
        pz[i] = xb[3 * p + 2];
        mind[i] = __int_as_float(0x7f800000);  // +inf
    }

    int cur = 0;
    for (int g = 0; g < Gn; g++) {
        // current center coords (uniform load, L1/L2-hot)
        float cx = __ldg(xb + 3 * cur + 0);
        float cy = __ldg(xb + 3 * cur + 1);
        float cz = __ldg(xb + 3 * cur + 2);
        if (tid == 0) {
            float* c = centers + ((long)b * Gn + g) * 3;
            c[0] = cx; c[1] = cy; c[2] = cz;
        }

        unsigned long long best = 0ull;
#pragma unroll
        for (int i = 0; i < 8; i++) {
            float dx = px[i] - cx, dy = py[i] - cy, dz = pz[i] - cz;
            float d  = dx * dx + dy * dy + dz * dz;
            float m  = fminf(mind[i], d);
            mind[i]  = m;
            unsigned long long pk =
                ((unsigned long long)__float_as_uint(m) << 32) |
                (unsigned)(Nn - 1 - (tid * 8 + i));
            best = (pk > best) ? pk : best;
        }
        // warp max-reduce
#pragma unroll
        for (int off = 16; off; off >>= 1) {
            unsigned long long o = __shfl_xor_sync(FULLMASK, best, off);
            best = (o > best) ? o : best;
        }
        if (lane == 0) warpbest[wid] = best;
        __syncthreads();
        if (wid == 0) {
            unsigned long long bb = warpbest[lane];
#pragma unroll
            for (int off = 16; off; off >>= 1) {
                unsigned long long o = __shfl_xor_sync(FULLMASK, bb, off);
                bb = (o > bb) ? o : bb;
            }
            if (lane == 0) finalbest = bb;
        }
        __syncthreads();
        cur = Nn - 1 - (int)(unsigned)(finalbest & 0xFFFFFFFFull);
    }
}

// ---------------------------------------------------------------------------
// Kernel 2: exact ordered top-32 neighbors per group + recentered gather.
// 8 warps / block, one warp per group, 8 groups of the same batch per block.
// Warp-collective top-32: each lane owns one (val, idx) slot; tau = current
// 32nd smallest; insertions gated by key < tau (expected ~178 per group).
// ---------------------------------------------------------------------------
__global__ __launch_bounds__(256, 4) void knn_kernel(const float* __restrict__ xyz,
                                                     const float* __restrict__ centers,
                                                     float* __restrict__ patch)
{
    __shared__ float spts[2048 * 3];  // 24 KB chunk of points

    const int b     = blockIdx.x >> 5;        // 32 blocks per batch
    const int gbase = (blockIdx.x & 31) * 8;
    const int wid   = threadIdx.x >> 5;
    const int lane  = threadIdx.x & 31;
    const int g     = gbase + wid;

    const float* cptr = centers + ((long)b * Gn + g) * 3;
    float cx = cptr[0], cy = cptr[1], cz = cptr[2];

    float    sval = __int_as_float(0x7f800000);  // slot value (+inf = empty)
    unsigned sidx = 0xFFFFFFFFu;                 // slot index
    float    tau  = __int_as_float(0x7f800000);  // current max of the 32 slots
    int      tauOwner = 0;

    for (int c = 0; c < 4; c++) {
        __syncthreads();
        // cooperative chunk stage: 2048 pts * 3 floats = 1536 float4
        const float4* src4 = (const float4*)(xyz + ((long)b * Nn + c * 2048) * 3);
        float4* dst4 = (float4*)spts;
        for (int i = threadIdx.x; i < 1536; i += 256) dst4[i] = src4[i];
        __syncthreads();

        for (int s = 0; s < 64; s++) {
            int p = s * 32 + lane;
            float x = spts[3 * p + 0];
            float y = spts[3 * p + 1];
            float z = spts[3 * p + 2];
            float dx = cx - x, dy = cy - y, dz = cz - z;
            float key = dx * dx + dy * dy + dz * dz;
            unsigned gi = (unsigned)(c * 2048 + p);
            unsigned kb = __float_as_uint(key);

            unsigned act = __ballot_sync(FULLMASK, key < tau);
            while (act) {
                // min (key, idx) among active candidates (lane asc == idx asc)
                unsigned v  = ((act >> lane) & 1u) ? kb : 0xFFFFFFFFu;
                unsigned mn = __reduce_min_sync(FULLMASK, v);
                unsigned eq = __ballot_sync(FULLMASK, v == mn);
                int src_l   = __ffs(eq) - 1;
                unsigned ni = __shfl_sync(FULLMASK, gi, src_l);
                // evict current lex-max slot, insert candidate
                if (lane == tauOwner) { sval = __uint_as_float(mn); sidx = ni; }
                // recompute tau = lex-max (valbits, idx) over slots
                unsigned sb  = __float_as_uint(sval);
                unsigned mx  = __reduce_max_sync(FULLMASK, sb);
                bool ismx    = (sb == mx);
                unsigned ci  = ismx ? sidx : 0u;
                unsigned mi  = __reduce_max_sync(FULLMASK, ci);
                unsigned em2 = __ballot_sync(FULLMASK, ismx && (sidx == mi));
                tauOwner = __ffs(em2) - 1;
                tau = __uint_as_float(mx);
                // drop inserted candidate; re-filter by new tau
                act &= ~(1u << src_l);
                act = __ballot_sync(FULLMASK, ((act >> lane) & 1u) && (key < tau));
            }
        }
    }

    // rank each slot by (val, idx) lex order; ranks are a permutation of 0..31
    unsigned long long mypack =
        ((unsigned long long)__float_as_uint(sval) << 32) | (unsigned long long)sidx;
    int rank = 0;
#pragma unroll
    for (int j = 0; j < 32; j++) {
        unsigned long long o = __shfl_sync(FULLMASK, mypack, j);
        rank += (o < mypack) ? 1 : 0;
    }

    const float* pp = xyz + ((long)b * Nn + sidx) * 3;
    float* outp = patch + (((long)(b * Gn + g) * Kn) + rank) * 3;
    outp[0] = pp[0] - cx;
    outp[1] = pp[1] - cy;
    outp[2] = pp[2] - cz;
}

// ---------------------------------------------------------------------------
extern "C" void kernel_launch(void* const* d_in, const int* in_sizes, int n_in,
                              void* d_out, int out_size)
{
    (void)in_sizes; (void)n_in; (void)out_size;
    const float* xyz = (const float*)d_in[0];
    float* out     = (float*)d_out;
    float* patch   = out;                       // (B, G, K, 3)
    float* centers = out + (long)Bn * Gn * Kn * 3;  // (B, G, 3)

    fps_kernel<<<Bn, 1024>>>(xyz, centers);
    knn_kernel<<<(Bn * Gn) / 8, 256>>>(xyz, centers, patch);
}

// round 8
// speedup vs baseline: 1.3606x; 1.3606x over previous
#include <cuda_runtime.h>
#include <cuda_bf16.h>

#define Bn 32
#define Nn 8192
#define Gn 256
#define Kn 32
#define CH 1024
#define FULLMASK 0xFFFFFFFFu

// ---------------------------------------------------------------------------
// Kernel 1: farthest point sampling. One block per batch, 1024 threads,
// 8 points/thread in registers. Distance = sub-then-square (bit-compatible
// with reference trajectory). Value-only block max via redux.sync; index
// recovered by rare claimant rescan + shared atomicMin (first-index
// tie-break == jnp.argmax).
// ---------------------------------------------------------------------------
__global__ __launch_bounds__(1024, 1) void fps_kernel(const float* __restrict__ xyz,
                                                      float* __restrict__ centers)
{
    __shared__ unsigned warpmax[32];
    __shared__ unsigned s_wm;
    __shared__ unsigned s_idx;

    const int b    = blockIdx.x;
    const int tid  = threadIdx.x;
    const int lane = tid & 31;
    const int wid  = tid >> 5;
    const float* xb = xyz + (size_t)b * Nn * 3;

    // load 8 points = 24 floats = 6 float4 (tid*96 bytes, 16B aligned)
    float px[8], py[8], pz[8], mind[8];
    {
        float c[24];
        const float4* s4 = (const float4*)(xb + tid * 24);
#pragma unroll
        for (int q = 0; q < 6; q++) {
            float4 v = s4[q];
            c[4 * q + 0] = v.x; c[4 * q + 1] = v.y;
            c[4 * q + 2] = v.z; c[4 * q + 3] = v.w;
        }
#pragma unroll
        for (int i = 0; i < 8; i++) {
            px[i] = c[3 * i + 0];
            py[i] = c[3 * i + 1];
            pz[i] = c[3 * i + 2];
            mind[i] = __int_as_float(0x7f800000);  // +inf
        }
    }

    int cur = 0;
    for (int g = 0; g < Gn; g++) {
        float cx = __ldg(xb + 3 * cur + 0);
        float cy = __ldg(xb + 3 * cur + 1);
        float cz = __ldg(xb + 3 * cur + 2);
        if (tid == 0) {
            float* cp = centers + ((size_t)b * Gn + g) * 3;
            cp[0] = cx; cp[1] = cy; cp[2] = cz;
        }

        float vm = 0.0f;
#pragma unroll
        for (int i = 0; i < 8; i++) {
            // EXACT round-1 arithmetic: sub then square (reference-matching)
            float dx = px[i] - cx, dy = py[i] - cy, dz = pz[i] - cz;
            float d  = dx * dx + dy * dy + dz * dz;
            float m  = fminf(mind[i], d);
            mind[i]  = m;
            vm = fmaxf(vm, m);
        }
        // distances >= 0 so bit-compare == float-compare
        unsigned vb   = __float_as_uint(vm);
        unsigned wmax = __reduce_max_sync(FULLMASK, vb);
        if (lane == 0) warpmax[wid] = wmax;
        __syncthreads();
        if (wid == 0) {
            unsigned w  = warpmax[lane];
            unsigned bm = __reduce_max_sync(FULLMASK, w);
            if (lane == 0) { s_wm = bm; s_idx = 0xFFFFFFFFu; }
        }
        __syncthreads();
        unsigned wm = s_wm;
        if (vb == wm) {
            int j = -1;
#pragma unroll
            for (int i = 7; i >= 0; i--)
                if (__float_as_uint(mind[i]) == wm) j = i;
            if (j >= 0) atomicMin(&s_idx, (unsigned)(tid * 8 + j));
        }
        __syncthreads();
        cur = (int)s_idx;
    }
}

// ---------------------------------------------------------------------------
// Kernel 2: exact ordered top-32 per group. One warp per group, slots kept
// sorted ascending across lanes by (valbits, idx); lane 31 always holds tau.
// Insert = broadcast + ballot-prefix shift (~6 collectives). rank == lane.
// Key arithmetic identical to the round-1 passing kernel.
// ---------------------------------------------------------------------------
__global__ __launch_bounds__(256, 6) void knn_kernel(const float* __restrict__ xyz,
                                                     const float* __restrict__ centers,
                                                     float* __restrict__ patch)
{
    __shared__ float spts[CH * 3];  // 12 KB chunk

    const int b     = blockIdx.x >> 5;        // 32 blocks per batch
    const int gbase = (blockIdx.x & 31) * 8;
    const int wid   = threadIdx.x >> 5;
    const int lane  = threadIdx.x & 31;
    const int g     = gbase + wid;

    const float* cptr = centers + ((size_t)b * Gn + g) * 3;
    float cx = cptr[0], cy = cptr[1], cz = cptr[2];

    // slot: packed (distbits<<32)|idx, sorted ascending by lane
    unsigned long long slot =
        ((unsigned long long)0x7f800000u << 32) | 0xFFFFFFFFull;
    unsigned taub = 0x7f800000u;  // +inf bits

    for (int c = 0; c < Nn / CH; c++) {
        __syncthreads();
        const float4* src4 = (const float4*)(xyz + ((size_t)b * Nn + c * CH) * 3);
        float4* dst4 = (float4*)spts;
        for (int i = threadIdx.x; i < CH * 3 / 4; i += 256) dst4[i] = src4[i];
        __syncthreads();

        for (int s = 0; s < CH / 32; s++) {
            int p = s * 32 + lane;
            float x = spts[3 * p + 0];
            float y = spts[3 * p + 1];
            float z = spts[3 * p + 2];
            // EXACT round-1 arithmetic
            float dx = cx - x, dy = cy - y, dz = cz - z;
            float key = dx * dx + dy * dy + dz * dz;
            unsigned kb = __float_as_uint(key);
            unsigned gi = (unsigned)(c * CH + p);

            // bit compare == float compare for non-negative floats
            unsigned act = __ballot_sync(FULLMASK, kb < taub);
            while (act) {
                int src = __ffs(act) - 1;
                act &= act - 1;
                unsigned ckb = __shfl_sync(FULLMASK, kb, src);
                unsigned cgi = __shfl_sync(FULLMASK, gi, src);
                if (ckb >= taub) continue;  // uniform: tau dropped below it
                unsigned long long cpk =
                    ((unsigned long long)ckb << 32) | cgi;
                bool gtp = slot > cpk;
                unsigned bal = __ballot_sync(FULLMASK, gtp);
                int pos = __ffs(bal) - 1;  // always >= 0: lane31 slot > cpk
                unsigned long long up = __shfl_up_sync(FULLMASK, slot, 1);
                unsigned long long ns = gtp ? up : slot;
                if (lane == pos) ns = cpk;
                slot = ns;
                taub = __shfl_sync(FULLMASK, (unsigned)(slot >> 32), 31);
            }
        }
    }

    // slots sorted: rank == lane
    unsigned sidx = (unsigned)(slot & 0xFFFFFFFFull);
    const float* pp = xyz + ((size_t)b * Nn + sidx) * 3;
    float* outp = patch + (((size_t)(b * Gn + g)) * Kn + lane) * 3;
    outp[0] = pp[0] - cx;
    outp[1] = pp[1] - cy;
    outp[2] = pp[2] - cz;
}

// ---------------------------------------------------------------------------
extern "C" void kernel_launch(void* const* d_in, const int* in_sizes, int n_in,
                              void* d_out, int out_size)
{
    (void)in_sizes; (void)n_in; (void)out_size;
    const float* xyz = (const float*)d_in[0];
    float* out     = (float*)d_out;
    float* patch   = out;                           // (B, G, K, 3)
    float* centers = out + (size_t)Bn * Gn * Kn * 3;  // (B, G, 3)

    fps_kernel<<<Bn, 1024>>>(xyz, centers);
    knn_kernel<<<(Bn * Gn) / 8, 256>>>(xyz, centers, patch);
}